// round 9
// baseline (speedup 1.0000x reference)
#include <cuda_runtime.h>
#include <cstdint>

#define T_DIM  4096
#define B_DIM  8192
#define CHUNKS 128
#define CL     32          // chunk length; CHUNKS*CL == T_DIM

// Scratch: static device globals (allocation-free). 16 MB total.
__device__ uint32_t g_bits[CHUNKS * B_DIM];          // 4 MB packed inputs
__device__ float    g_state[3][CHUNKS * B_DIM];      // 12 MB chunk states (n1tot, n11, na1)

// ---------------------------------------------------------------------------
// Pass 1: per-chunk local recurrence; pack input bits.
// 4 seqs/thread, plain float4 loads, full unroll; occupancy forced to 6 CTA/SM.
// ---------------------------------------------------------------------------
__global__ void __launch_bounds__(256, 6) lk_pass1(const float* __restrict__ in,
                                                   const float* __restrict__ dptr) {
    const float d = dptr[0];
    const int c  = blockIdx.y;
    const int g  = blockIdx.x * blockDim.x + threadIdx.x;
    const int b0 = g * 4;

    float prev_d[4] = {0.f, 0.f, 0.f, 0.f};
    if (c != 0) {
        float4 pv = *(const float4*)(in + (size_t)(c * CL - 1) * B_DIM + b0);
        prev_d[0] = pv.x * d; prev_d[1] = pv.y * d;
        prev_d[2] = pv.z * d; prev_d[3] = pv.w * d;
    }

    float n1t[4] = {0.f, 0.f, 0.f, 0.f};   // n10 + n11
    float n11[4] = {0.f, 0.f, 0.f, 0.f};
    float na1[4] = {0.f, 0.f, 0.f, 0.f};
    uint32_t bw[4] = {0u, 0u, 0u, 0u};

    const float4* __restrict__ p = (const float4*)(in + (size_t)(c * CL) * B_DIM + b0);

#pragma unroll
    for (int i = 0; i < CL; ++i) {
        float4 x4 = p[(size_t)i * (B_DIM / 4)];
        float xs[4] = {x4.x, x4.y, x4.z, x4.w};
#pragma unroll
        for (int s = 0; s < 4; ++s) {
            float curf = xs[s];                    // 0.0f or 1.0f
            if (curf != 0.f) bw[s] |= (1u << i);
            float cur_d = curf * d;
            n11[s] = fmaf(d, n11[s], curf * prev_d[s]);
            na1[s] = fmaf(d, na1[s], prev_d[s]);
            n1t[s] = fmaf(d, n1t[s], cur_d);
            prev_d[s] = cur_d;
        }
    }

    *(uint4*)(g_bits + (size_t)c * B_DIM + b0) = make_uint4(bw[0], bw[1], bw[2], bw[3]);
    const size_t si = (size_t)c * B_DIM + b0;
    *(float4*)(&g_state[0][si]) = make_float4(n1t[0], n1t[1], n1t[2], n1t[3]);
    *(float4*)(&g_state[1][si]) = make_float4(n11[0], n11[1], n11[2], n11[3]);
    *(float4*)(&g_state[2][si]) = make_float4(na1[0], na1[1], na1[2], na1[3]);
}

// ---------------------------------------------------------------------------
// Pass 2: exclusive scan over chunk states: carry_c = local_c + d^CL * carry_{c-1}.
// ---------------------------------------------------------------------------
__global__ void __launch_bounds__(256) lk_pass2(const float* __restrict__ dptr) {
    const float d = dptr[0];
    float dL = d;
#pragma unroll
    for (int i = 0; i < 5; ++i) dL *= dL;  // d^32

    const int comp = blockIdx.y;  // 0..2
    const int b    = blockIdx.x * blockDim.x + threadIdx.x;
    float* a = g_state[comp];

    float acc = 0.f;
#pragma unroll
    for (int batch = 0; batch < CHUNKS / 32; ++batch) {
        float v[32];
#pragma unroll
        for (int j = 0; j < 32; ++j)
            v[j] = a[(size_t)(batch * 32 + j) * B_DIM + b];
#pragma unroll
        for (int j = 0; j < 32; ++j) {
            float nv = fmaf(dL, acc, v[j]);
            v[j] = acc;           // exclusive prefix
            acc = nv;
        }
#pragma unroll
        for (int j = 0; j < 32; ++j)
            a[(size_t)(batch * 32 + j) * B_DIM + b] = v[j];
    }
}

// ---------------------------------------------------------------------------
// Pass 3: replay from corrected init; emit predictions.
// 2 seqs/thread, STG.64.cs streaming stores, 4096 blocks of 128 threads.
// ---------------------------------------------------------------------------
__global__ void __launch_bounds__(128, 12) lk_pass3(const float* __restrict__ dptr,
                                                    float* __restrict__ out) {
    const float d = dptr[0];
    const int c  = blockIdx.y;
    const int t  = blockIdx.x * blockDim.x + threadIdx.x;
    const int b0 = t * 2;
    const size_t si = (size_t)c * B_DIM + b0;

    float2 v1t = *(const float2*)(&g_state[0][si]);
    float2 v11 = *(const float2*)(&g_state[1][si]);
    float2 va1 = *(const float2*)(&g_state[2][si]);
    float n1t[2] = {v1t.x, v1t.y};
    float n11[2] = {v11.x, v11.y};
    float na1[2] = {va1.x, va1.y};

    // Deterministic total-count carry-in: S = d * (1 - d^{c*CL}) / (1 - d)
    float dL = d;
#pragma unroll
    for (int i = 0; i < 5; ++i) dL *= dL;   // d^CL
    float dcs = 1.f, base = dL;
    int e = c;
    while (e) { if (e & 1) dcs *= base; base *= base; e >>= 1; }
    float S = (c == 0) ? 0.f : d * (1.f - dcs) / (1.f - d);

    float prev_d[2] = {0.f, 0.f};
    if (c != 0) {
        uint2 pw = *(const uint2*)(g_bits + (size_t)(c - 1) * B_DIM + b0);
        prev_d[0] = (pw.x >> 31) ? d : 0.f;
        prev_d[1] = (pw.y >> 31) ? d : 0.f;
    }

    uint2 bwv = *(const uint2*)(g_bits + (size_t)c * B_DIM + b0);
    uint32_t bw[2] = {bwv.x, bwv.y};

    float2* __restrict__ po = (float2*)(out + (size_t)(c * CL) * B_DIM + b0);

#pragma unroll
    for (int i = 0; i < CL; ++i) {
        S = fmaf(d, S, d);  // shared across the sequences
        float ov[2];
#pragma unroll
        for (int s = 0; s < 2; ++s) {
            bool cur = (bw[s] >> i) & 1u;
            float cur_d = cur ? d : 0.f;
            n11[s] = fmaf(d, n11[s], cur ? prev_d[s] : 0.f);
            na1[s] = fmaf(d, na1[s], prev_d[s]);
            n1t[s] = fmaf(d, n1t[s], cur_d);
            prev_d[s] = cur_d;
            float num = (cur ? n11[s] : n1t[s] - n11[s]) + 1.f;
            float den = (cur ? na1[s] : S - na1[s]) + 2.f;
            ov[s] = __fdividef(num, den);
        }
        __stcs(po + (size_t)i * (B_DIM / 2), make_float2(ov[0], ov[1]));
    }
}

// ---------------------------------------------------------------------------
extern "C" void kernel_launch(void* const* d_in, const int* in_sizes, int n_in,
                              void* d_out, int out_size) {
    const float* in   = (const float*)d_in[0];
    const float* dptr = (const float*)d_in[1];
    if (n_in >= 2 && in_sizes[0] == 1) {  // defensive: metadata order swap
        in   = (const float*)d_in[1];
        dptr = (const float*)d_in[0];
    }
    float* out = (float*)d_out;

    dim3 grid1((B_DIM / 4) / 256, CHUNKS);   // (8, 128), 256 tpb
    dim3 grid2(B_DIM / 256, 3);              // (32, 3),  256 tpb
    dim3 grid3((B_DIM / 2) / 128, CHUNKS);   // (32, 128), 128 tpb = 4096 blocks

    lk_pass1<<<grid1, 256>>>(in, dptr);
    lk_pass2<<<grid2, 256>>>(dptr);
    lk_pass3<<<grid3, 128>>>(dptr, out);
}

// round 10
// speedup vs baseline: 1.0021x; 1.0021x over previous
#include <cuda_runtime.h>
#include <cstdint>

#define T_DIM  4096
#define B_DIM  8192
#define CHUNKS 128
#define CL     32          // chunk length; CHUNKS*CL == T_DIM
#define SGC    4           // chunks per supergroup
#define NSG    (CHUNKS / SGC)   // 32 supergroups (128 steps each)

// Scratch: static device globals (allocation-free).
__device__ uint32_t g_bits[CHUNKS * B_DIM];          // 4 MB packed inputs (1 word/chunk/seq)
__device__ float    g_state[3][CHUNKS * B_DIM];      // 12 MB chunk-local aggregates
__device__ float    g_carry[3][NSG * B_DIM];         // 3 MB supergroup carry-ins

// ---------------------------------------------------------------------------
// Pass 1 (R3-proven config, untouched): per-chunk local recurrence; pack bits.
// 4 seqs/thread, plain float4 loads, full unroll.
// ---------------------------------------------------------------------------
__global__ void __launch_bounds__(256) lk_pass1(const float* __restrict__ in,
                                                const float* __restrict__ dptr) {
    const float d = dptr[0];
    const int c  = blockIdx.y;
    const int g  = blockIdx.x * blockDim.x + threadIdx.x;
    const int b0 = g * 4;

    float prev_d[4] = {0.f, 0.f, 0.f, 0.f};
    if (c != 0) {
        float4 pv = *(const float4*)(in + (size_t)(c * CL - 1) * B_DIM + b0);
        prev_d[0] = pv.x * d; prev_d[1] = pv.y * d;
        prev_d[2] = pv.z * d; prev_d[3] = pv.w * d;
    }

    float n1t[4] = {0.f, 0.f, 0.f, 0.f};   // n10 + n11
    float n11[4] = {0.f, 0.f, 0.f, 0.f};
    float na1[4] = {0.f, 0.f, 0.f, 0.f};
    uint32_t bw[4] = {0u, 0u, 0u, 0u};

    const float4* __restrict__ p = (const float4*)(in + (size_t)(c * CL) * B_DIM + b0);

#pragma unroll
    for (int i = 0; i < CL; ++i) {
        float4 x4 = p[(size_t)i * (B_DIM / 4)];
        float xs[4] = {x4.x, x4.y, x4.z, x4.w};
#pragma unroll
        for (int s = 0; s < 4; ++s) {
            float curf = xs[s];                    // 0.0f or 1.0f
            if (curf != 0.f) bw[s] |= (1u << i);
            float cur_d = curf * d;
            n11[s] = fmaf(d, n11[s], curf * prev_d[s]);
            na1[s] = fmaf(d, na1[s], prev_d[s]);
            n1t[s] = fmaf(d, n1t[s], cur_d);
            prev_d[s] = cur_d;
        }
    }

    *(uint4*)(g_bits + (size_t)c * B_DIM + b0) = make_uint4(bw[0], bw[1], bw[2], bw[3]);
    const size_t si = (size_t)c * B_DIM + b0;
    *(float4*)(&g_state[0][si]) = make_float4(n1t[0], n1t[1], n1t[2], n1t[3]);
    *(float4*)(&g_state[1][si]) = make_float4(n11[0], n11[1], n11[2], n11[3]);
    *(float4*)(&g_state[2][si]) = make_float4(na1[0], na1[1], na1[2], na1[3]);
}

// ---------------------------------------------------------------------------
// Pass 2: scan chunk aggregates; emit carry-ins ONLY at supergroup boundaries.
// carry[sg] = exclusive prefix before chunk sg*SGC  (12 MB read, 3 MB written)
// ---------------------------------------------------------------------------
__global__ void __launch_bounds__(256) lk_pass2(const float* __restrict__ dptr) {
    const float d = dptr[0];
    float dL = d;
#pragma unroll
    for (int i = 0; i < 5; ++i) dL *= dL;  // d^CL

    const int comp = blockIdx.y;  // 0..2
    const int b    = blockIdx.x * blockDim.x + threadIdx.x;
    const float* a = g_state[comp];
    float* cr = g_carry[comp];

    float acc = 0.f;
#pragma unroll
    for (int batch = 0; batch < CHUNKS / 32; ++batch) {
        float v[32];
#pragma unroll
        for (int j = 0; j < 32; ++j)
            v[j] = a[(size_t)(batch * 32 + j) * B_DIM + b];
#pragma unroll
        for (int j = 0; j < 32; ++j) {
            int cj = batch * 32 + j;
            if ((cj & (SGC - 1)) == 0)
                cr[(size_t)(cj / SGC) * B_DIM + b] = acc;
            acc = fmaf(dL, acc, v[j]);
        }
    }
}

// ---------------------------------------------------------------------------
// Pass 3: replay a full supergroup (SGC chunks = 128 steps) from one carry-in.
// 2 seqs/thread, STG.64.cs streaming stores. 1024 blocks x 128 threads.
// ---------------------------------------------------------------------------
__global__ void __launch_bounds__(128) lk_pass3(const float* __restrict__ dptr,
                                                float* __restrict__ out) {
    const float d = dptr[0];
    const int sg = blockIdx.y;                         // 0..NSG-1
    const int t  = blockIdx.x * blockDim.x + threadIdx.x;
    const int b0 = t * 2;
    const size_t ci = (size_t)sg * B_DIM + b0;

    float2 v1t = *(const float2*)(&g_carry[0][ci]);
    float2 v11 = *(const float2*)(&g_carry[1][ci]);
    float2 va1 = *(const float2*)(&g_carry[2][ci]);
    float n1t[2] = {v1t.x, v1t.y};
    float n11[2] = {v11.x, v11.y};
    float na1[2] = {va1.x, va1.y};

    // Deterministic total-count carry-in: S = d * (1 - d^{sg*SGC*CL}) / (1 - d)
    float dL = d;
#pragma unroll
    for (int i = 0; i < 7; ++i) dL *= dL;   // d^(SGC*CL) = d^128
    float dcs = 1.f, base = dL;
    int e = sg;
    while (e) { if (e & 1) dcs *= base; base *= base; e >>= 1; }
    float S = (sg == 0) ? 0.f : d * (1.f - dcs) / (1.f - d);

    // prev_d from last bit of the word preceding this supergroup
    float prev_d[2] = {0.f, 0.f};
    if (sg != 0) {
        uint2 pw = *(const uint2*)(g_bits + (size_t)(sg * SGC - 1) * B_DIM + b0);
        prev_d[0] = (pw.x >> 31) ? d : 0.f;
        prev_d[1] = (pw.y >> 31) ? d : 0.f;
    }

    float2* __restrict__ po = (float2*)(out + (size_t)(sg * SGC * CL) * B_DIM + b0);

#pragma unroll
    for (int w = 0; w < SGC; ++w) {
        uint2 bwv = *(const uint2*)(g_bits + (size_t)(sg * SGC + w) * B_DIM + b0);
        uint32_t bw[2] = {bwv.x, bwv.y};
#pragma unroll
        for (int i = 0; i < CL; ++i) {
            S = fmaf(d, S, d);  // shared across the sequences
            float ov[2];
#pragma unroll
            for (int s = 0; s < 2; ++s) {
                bool cur = (bw[s] >> i) & 1u;
                float cur_d = cur ? d : 0.f;
                n11[s] = fmaf(d, n11[s], cur ? prev_d[s] : 0.f);
                na1[s] = fmaf(d, na1[s], prev_d[s]);
                n1t[s] = fmaf(d, n1t[s], cur_d);
                prev_d[s] = cur_d;
                float num = (cur ? n11[s] : n1t[s] - n11[s]) + 1.f;
                float den = (cur ? na1[s] : S - na1[s]) + 2.f;
                ov[s] = __fdividef(num, den);
            }
            __stcs(po + (size_t)(w * CL + i) * (B_DIM / 2), make_float2(ov[0], ov[1]));
        }
    }
}

// ---------------------------------------------------------------------------
extern "C" void kernel_launch(void* const* d_in, const int* in_sizes, int n_in,
                              void* d_out, int out_size) {
    const float* in   = (const float*)d_in[0];
    const float* dptr = (const float*)d_in[1];
    if (n_in >= 2 && in_sizes[0] == 1) {  // defensive: metadata order swap
        in   = (const float*)d_in[1];
        dptr = (const float*)d_in[0];
    }
    float* out = (float*)d_out;

    dim3 grid1((B_DIM / 4) / 256, CHUNKS);   // (8, 128), 256 tpb
    dim3 grid2(B_DIM / 256, 3);              // (32, 3),  256 tpb
    dim3 grid3((B_DIM / 2) / 128, NSG);      // (32, 32), 128 tpb = 1024 blocks

    lk_pass1<<<grid1, 256>>>(in, dptr);
    lk_pass2<<<grid2, 256>>>(dptr);
    lk_pass3<<<grid3, 128>>>(dptr, out);
}

// round 11
// speedup vs baseline: 1.0479x; 1.0457x over previous
#include <cuda_runtime.h>
#include <cstdint>

#define T_DIM  4096
#define B_DIM  8192
#define CHUNKS 128
#define CL     32               // chunk length; CHUNKS*CL == T_DIM
#define SGC    2                // chunks per supergroup (pass3 replay unit)
#define NSG    (CHUNKS / SGC)   // 64 supergroups (64 steps each)

// Scratch: static device globals (allocation-free). 22 MB total.
__device__ uint32_t g_bits[CHUNKS * B_DIM];          // 4 MB packed inputs
__device__ float    g_state[3][CHUNKS * B_DIM];      // 12 MB chunk-local aggregates
__device__ float    g_carry[3][NSG * B_DIM];         // 6 MB supergroup carry-ins

// ---------------------------------------------------------------------------
// Pass 1 (R3-proven, untouched): per-chunk local recurrence; pack input bits.
// 4 seqs/thread, plain float4 loads, full unroll.
// ---------------------------------------------------------------------------
__global__ void __launch_bounds__(256) lk_pass1(const float* __restrict__ in,
                                                const float* __restrict__ dptr) {
    const float d = dptr[0];
    const int c  = blockIdx.y;
    const int g  = blockIdx.x * blockDim.x + threadIdx.x;
    const int b0 = g * 4;

    float prev_d[4] = {0.f, 0.f, 0.f, 0.f};
    if (c != 0) {
        float4 pv = *(const float4*)(in + (size_t)(c * CL - 1) * B_DIM + b0);
        prev_d[0] = pv.x * d; prev_d[1] = pv.y * d;
        prev_d[2] = pv.z * d; prev_d[3] = pv.w * d;
    }

    float n1t[4] = {0.f, 0.f, 0.f, 0.f};   // n10 + n11
    float n11[4] = {0.f, 0.f, 0.f, 0.f};
    float na1[4] = {0.f, 0.f, 0.f, 0.f};
    uint32_t bw[4] = {0u, 0u, 0u, 0u};

    const float4* __restrict__ p = (const float4*)(in + (size_t)(c * CL) * B_DIM + b0);

#pragma unroll
    for (int i = 0; i < CL; ++i) {
        float4 x4 = p[(size_t)i * (B_DIM / 4)];
        float xs[4] = {x4.x, x4.y, x4.z, x4.w};
#pragma unroll
        for (int s = 0; s < 4; ++s) {
            float curf = xs[s];                    // 0.0f or 1.0f
            if (curf != 0.f) bw[s] |= (1u << i);
            float cur_d = curf * d;
            n11[s] = fmaf(d, n11[s], curf * prev_d[s]);
            na1[s] = fmaf(d, na1[s], prev_d[s]);
            n1t[s] = fmaf(d, n1t[s], cur_d);
            prev_d[s] = cur_d;
        }
    }

    *(uint4*)(g_bits + (size_t)c * B_DIM + b0) = make_uint4(bw[0], bw[1], bw[2], bw[3]);
    const size_t si = (size_t)c * B_DIM + b0;
    *(float4*)(&g_state[0][si]) = make_float4(n1t[0], n1t[1], n1t[2], n1t[3]);
    *(float4*)(&g_state[1][si]) = make_float4(n11[0], n11[1], n11[2], n11[3]);
    *(float4*)(&g_state[2][si]) = make_float4(na1[0], na1[1], na1[2], na1[3]);
}

// ---------------------------------------------------------------------------
// Pass 2: scan chunk aggregates; emit carries only at supergroup boundaries.
// ---------------------------------------------------------------------------
__global__ void __launch_bounds__(256) lk_pass2(const float* __restrict__ dptr) {
    const float d = dptr[0];
    float dL = d;
#pragma unroll
    for (int i = 0; i < 5; ++i) dL *= dL;  // d^CL

    const int comp = blockIdx.y;  // 0..2
    const int b    = blockIdx.x * blockDim.x + threadIdx.x;
    const float* a = g_state[comp];
    float* cr = g_carry[comp];

    float acc = 0.f;
#pragma unroll
    for (int batch = 0; batch < CHUNKS / 32; ++batch) {
        float v[32];
#pragma unroll
        for (int j = 0; j < 32; ++j)
            v[j] = a[(size_t)(batch * 32 + j) * B_DIM + b];
#pragma unroll
        for (int j = 0; j < 32; ++j) {
            int cj = batch * 32 + j;
            if ((cj & (SGC - 1)) == 0)
                cr[(size_t)(cj / SGC) * B_DIM + b] = acc;   // exclusive prefix
            acc = fmaf(dL, acc, v[j]);
        }
    }
}

// ---------------------------------------------------------------------------
// Pass 3: replay a supergroup (2 chunks = 64 steps) from one carry-in.
// 2 seqs/thread, STG.64.cs streaming stores, 2048 blocks x 128 threads.
// ---------------------------------------------------------------------------
__global__ void __launch_bounds__(128) lk_pass3(const float* __restrict__ dptr,
                                                float* __restrict__ out) {
    const float d = dptr[0];
    const int sg = blockIdx.y;                         // 0..NSG-1
    const int t  = blockIdx.x * blockDim.x + threadIdx.x;
    const int b0 = t * 2;
    const size_t ci = (size_t)sg * B_DIM + b0;

    float2 v1t = *(const float2*)(&g_carry[0][ci]);
    float2 v11 = *(const float2*)(&g_carry[1][ci]);
    float2 va1 = *(const float2*)(&g_carry[2][ci]);
    float n1t[2] = {v1t.x, v1t.y};
    float n11[2] = {v11.x, v11.y};
    float na1[2] = {va1.x, va1.y};

    // Deterministic total-count carry-in: S = d * (1 - d^{sg*SGC*CL}) / (1 - d)
    float dL = d;
#pragma unroll
    for (int i = 0; i < 6; ++i) dL *= dL;   // d^(SGC*CL) = d^64
    float dcs = 1.f, base = dL;
    int e = sg;
    while (e) { if (e & 1) dcs *= base; base *= base; e >>= 1; }
    float S = (sg == 0) ? 0.f : d * (1.f - dcs) / (1.f - d);

    // prev_d from last bit of the word preceding this supergroup
    float prev_d[2] = {0.f, 0.f};
    if (sg != 0) {
        uint2 pw = *(const uint2*)(g_bits + (size_t)(sg * SGC - 1) * B_DIM + b0);
        prev_d[0] = (pw.x >> 31) ? d : 0.f;
        prev_d[1] = (pw.y >> 31) ? d : 0.f;
    }

    float2* __restrict__ po = (float2*)(out + (size_t)(sg * SGC * CL) * B_DIM + b0);

#pragma unroll
    for (int w = 0; w < SGC; ++w) {
        uint2 bwv = *(const uint2*)(g_bits + (size_t)(sg * SGC + w) * B_DIM + b0);
        uint32_t bw[2] = {bwv.x, bwv.y};
#pragma unroll
        for (int i = 0; i < CL; ++i) {
            S = fmaf(d, S, d);  // shared across the sequences
            float ov[2];
#pragma unroll
            for (int s = 0; s < 2; ++s) {
                bool cur = (bw[s] >> i) & 1u;
                float cur_d = cur ? d : 0.f;
                n11[s] = fmaf(d, n11[s], cur ? prev_d[s] : 0.f);
                na1[s] = fmaf(d, na1[s], prev_d[s]);
                n1t[s] = fmaf(d, n1t[s], cur_d);
                prev_d[s] = cur_d;
                float num = (cur ? n11[s] : n1t[s] - n11[s]) + 1.f;
                float den = (cur ? na1[s] : S - na1[s]) + 2.f;
                ov[s] = __fdividef(num, den);
            }
            __stcs(po + (size_t)(w * CL + i) * (B_DIM / 2), make_float2(ov[0], ov[1]));
        }
    }
}

// ---------------------------------------------------------------------------
extern "C" void kernel_launch(void* const* d_in, const int* in_sizes, int n_in,
                              void* d_out, int out_size) {
    const float* in   = (const float*)d_in[0];
    const float* dptr = (const float*)d_in[1];
    if (n_in >= 2 && in_sizes[0] == 1) {  // defensive: metadata order swap
        in   = (const float*)d_in[1];
        dptr = (const float*)d_in[0];
    }
    float* out = (float*)d_out;

    dim3 grid1((B_DIM / 4) / 256, CHUNKS);   // (8, 128), 256 tpb
    dim3 grid2(B_DIM / 256, 3);              // (32, 3),  256 tpb
    dim3 grid3((B_DIM / 2) / 128, NSG);      // (32, 64), 128 tpb = 2048 blocks

    lk_pass1<<<grid1, 256>>>(in, dptr);
    lk_pass2<<<grid2, 256>>>(dptr);
    lk_pass3<<<grid3, 128>>>(dptr, out);
}